// round 12
// baseline (speedup 1.0000x reference)
#include <cuda_runtime.h>
#include <math_constants.h>

// Problem constants (fixed by the reference)
#define BB 2
#define TT 512
#define EE 1024
#define SS 2048
#define AA 30

// Scratch for precomputed head scores: relu(x @ W + b), shape (B*T)
__device__ float g_scores[BB * TT];

// ---------------------------------------------------------------------------
// Kernel 1: scores[b,t] = relu(dot(x[b,t,:], W) + bias)
// One warp per row, ILP=8. 1024 rows -> 128 blocks x 8 warps.
// ---------------------------------------------------------------------------
__global__ __launch_bounds__(256)
void score_kernel(const float* __restrict__ x,
                  const float* __restrict__ W,
                  const float* __restrict__ bias) {
    const int row  = blockIdx.x * 8 + (threadIdx.x >> 5);   // B*T = 1024 rows
    const int lane = threadIdx.x & 31;

    const float4* __restrict__ xr = reinterpret_cast<const float4*>(x) + (size_t)row * 256;
    const float4* __restrict__ w4 = reinterpret_cast<const float4*>(W);

    float acc = 0.0f;
#pragma unroll
    for (int i = 0; i < 8; ++i) {
        const float4 xv = xr[lane + i * 32];
        const float4 wv = w4[lane + i * 32];
        acc += xv.x * wv.x + xv.y * wv.y + xv.z * wv.z + xv.w * wv.w;
    }
#pragma unroll
    for (int off = 16; off; off >>= 1)
        acc += __shfl_xor_sync(0xffffffffu, acc, off);

    if (lane == 0)
        g_scores[row] = fmaxf(acc + bias[0], 0.0f);
}

// ---------------------------------------------------------------------------
// Kernel 2: block per (s, b), 256 threads.
//   warp 0: softmax over <=30 valid scores -> smem p[32], zero-padded
//   main loop: double-buffered x4 batches -> next 4 row loads issue BEFORE
//   the current batch's FMAs, steady-state MLP = 8 per thread.
//   Row indices clamped to T-1 (p[j] = 0 past w keeps the math exact).
// ---------------------------------------------------------------------------
__global__ __launch_bounds__(256)
void span_kernel(const float* __restrict__ x,
                 const int* __restrict__ start,
                 const int* __restrict__ end,
                 float* __restrict__ out) {
    const int s = blockIdx.x;
    const int b = blockIdx.y;

    const int t0 = start[s];
    const int w  = end[s] - t0 + 1;   // 1..30

    __shared__ float p[32];

    const int tid = threadIdx.x;
    if (tid < 32) {
        const float sc = (tid < w) ? g_scores[b * TT + t0 + tid] : -CUDART_INF_F;
        float m = sc;
#pragma unroll
        for (int off = 16; off; off >>= 1)
            m = fmaxf(m, __shfl_xor_sync(0xffffffffu, m, off));
        const float e = (tid < w) ? __expf(sc - m) : 0.0f;
        float sum = e;
#pragma unroll
        for (int off = 16; off; off >>= 1)
            sum += __shfl_xor_sync(0xffffffffu, sum, off);
        p[tid] = e / sum;             // exactly 0 for tid >= w
    }
    __syncthreads();

    // Each thread owns one float4 column of E (256 * 4 = 1024).
    const float4* __restrict__ xb =
        reinterpret_cast<const float4*>(x) + (size_t)b * TT * 256 + tid;

    float4 acc = make_float4(0.0f, 0.0f, 0.0f, 0.0f);

    // ---- prime batch 0 (rows 0..3, clamped) ----
    float4 v0 = xb[(size_t)min(t0,     TT - 1) * 256];
    float4 v1 = xb[(size_t)min(t0 + 1, TT - 1) * 256];
    float4 v2 = xb[(size_t)min(t0 + 2, TT - 1) * 256];
    float4 v3 = xb[(size_t)min(t0 + 3, TT - 1) * 256];
    float p0 = p[0], p1 = p[1], p2 = p[2], p3 = p[3];

#pragma unroll 1
    for (int j = 4; j < w; j += 4) {
        // issue next batch's loads first (overlap with FMAs below)
        const float4 n0 = xb[(size_t)min(t0 + j,     TT - 1) * 256];
        const float4 n1 = xb[(size_t)min(t0 + j + 1, TT - 1) * 256];
        const float4 n2 = xb[(size_t)min(t0 + j + 2, TT - 1) * 256];
        const float4 n3 = xb[(size_t)min(t0 + j + 3, TT - 1) * 256];
        const float q0 = p[j], q1 = p[j + 1], q2 = p[j + 2], q3 = p[j + 3];

        acc.x += p0 * v0.x + p1 * v1.x + p2 * v2.x + p3 * v3.x;
        acc.y += p0 * v0.y + p1 * v1.y + p2 * v2.y + p3 * v3.y;
        acc.z += p0 * v0.z + p1 * v1.z + p2 * v2.z + p3 * v3.z;
        acc.w += p0 * v0.w + p1 * v1.w + p2 * v2.w + p3 * v3.w;

        v0 = n0; v1 = n1; v2 = n2; v3 = n3;
        p0 = q0; p1 = q1; p2 = q2; p3 = q3;
    }

    // ---- drain last batch ----
    acc.x += p0 * v0.x + p1 * v1.x + p2 * v2.x + p3 * v3.x;
    acc.y += p0 * v0.y + p1 * v1.y + p2 * v2.y + p3 * v3.y;
    acc.z += p0 * v0.z + p1 * v1.z + p2 * v2.z + p3 * v3.z;
    acc.w += p0 * v0.w + p1 * v1.w + p2 * v2.w + p3 * v3.w;

    reinterpret_cast<float4*>(out)[((size_t)b * SS + s) * 256 + tid] = acc;
}

// ---------------------------------------------------------------------------
// Launch
// Inputs (metadata order): x (B,T,E) f32, W (E,1) f32, b (1,) f32,
//                          start (S,) i32, end (S,) i32
// Output: (B, S, E) f32
// ---------------------------------------------------------------------------
extern "C" void kernel_launch(void* const* d_in, const int* in_sizes, int n_in,
                              void* d_out, int out_size) {
    const float* x     = (const float*)d_in[0];
    const float* W     = (const float*)d_in[1];
    const float* bias  = (const float*)d_in[2];
    const int*   start = (const int*)d_in[3];
    const int*   end   = (const int*)d_in[4];
    float*       out   = (float*)d_out;

    // Kernel 1: scores, warp per row
    score_kernel<<<(BB * TT) / 8, 256>>>(x, W, bias);

    // Kernel 2: block per (span, batch), pipelined gather
    dim3 grid(SS, BB);
    span_kernel<<<grid, 256>>>(x, start, end, out);
}

// round 13
// speedup vs baseline: 1.0307x; 1.0307x over previous
#include <cuda_runtime.h>
#include <math_constants.h>

// Problem constants (fixed by the reference)
#define BB 2
#define TT 512
#define EE 1024
#define SS 2048
#define AA 30

#define GSZ 4
#define NB2 (TT * 4)          // quantized sort key: t0*4 + (w-1)/8
#define NGROUPS_MAX 896       // sum ceil(n_t/4) <= (2048 + 3*512)/4

__device__ float g_scores[BB * TT];
__device__ float g_probs[BB * SS * 32];
__device__ int   g_sorted[SS];
__device__ int4  g_groups[NGROUPS_MAX];
__device__ int   g_ngroups;

// ---------------------------------------------------------------------------
// Kernel 1: scores[b,t] = relu(dot(x[b,t,:], W) + bias). Warp per row, ILP=8.
// ---------------------------------------------------------------------------
__global__ __launch_bounds__(256)
void score_kernel(const float* __restrict__ x,
                  const float* __restrict__ W,
                  const float* __restrict__ bias) {
    const int row  = blockIdx.x * 8 + (threadIdx.x >> 5);   // B*T = 1024 rows
    const int lane = threadIdx.x & 31;

    const float4* __restrict__ xr = reinterpret_cast<const float4*>(x) + (size_t)row * 256;
    const float4* __restrict__ w4 = reinterpret_cast<const float4*>(W);

    float acc = 0.0f;
#pragma unroll
    for (int i = 0; i < 8; ++i) {
        const float4 xv = xr[lane + i * 32];
        const float4 wv = w4[lane + i * 32];
        acc += xv.x * wv.x + xv.y * wv.y + xv.z * wv.z + xv.w * wv.w;
    }
#pragma unroll
    for (int off = 16; off; off >>= 1)
        acc += __shfl_xor_sync(0xffffffffu, acc, off);

    if (lane == 0)
        g_scores[row] = fmaxf(acc + bias[0], 0.0f);
}

// ---------------------------------------------------------------------------
// Kernel 2: softmax probs per (b,s) -> g_probs[b][s][lane], 0 for lane >= w.
// ---------------------------------------------------------------------------
__global__ __launch_bounds__(256)
void prob_kernel(const int* __restrict__ start,
                 const int* __restrict__ end) {
    const int wid  = blockIdx.x * 8 + (threadIdx.x >> 5);   // 0 .. B*S-1
    const int lane = threadIdx.x & 31;
    const int s = wid & (SS - 1);
    const int b = wid >> 11;

    const int t0 = start[s];
    const int w  = end[s] - t0 + 1;                          // 1..30

    float sc = (lane < w) ? g_scores[b * TT + t0 + lane] : -CUDART_INF_F;
    float m = sc;
#pragma unroll
    for (int off = 16; off; off >>= 1)
        m = fmaxf(m, __shfl_xor_sync(0xffffffffu, m, off));
    float e = (lane < w) ? __expf(sc - m) : 0.0f;
    float sum = e;
#pragma unroll
    for (int off = 16; off; off >>= 1)
        sum += __shfl_xor_sync(0xffffffffu, sum, off);

    g_probs[((size_t)b * SS + s) * 32 + lane] = e / sum;     // exactly 0 past w
}

// ---------------------------------------------------------------------------
// Kernel 3: counting sort of spans by quantized key (t0, w-tier) + groups.
// Single block, 1024 threads, 2048 bins in static smem.
// Groups of <=4 spans per t0, w-tier sorted -> tight per-group wmax.
// Group order is deterministic (exclusive scan); membership within a
// (t0,tier) bin is atomic-ordered but results are order-invariant (each
// span's math is independent of its group).
// ---------------------------------------------------------------------------
__global__ __launch_bounds__(1024)
void sort_kernel(const int* __restrict__ start,
                 const int* __restrict__ end) {
    __shared__ int bins[NB2];            // 8 KB
    __shared__ int t0_off[TT + 1];
    __shared__ int aux[32];
    __shared__ int aux2[32];

    const int tid  = threadIdx.x;
    const int lane = tid & 31;
    const int wrp  = tid >> 5;

    for (int i = tid; i < NB2; i += 1024) bins[i] = 0;
    __syncthreads();

    // histogram over (t0, w-tier)
    for (int s = tid; s < SS; s += 1024) {
        const int t0 = start[s];
        const int w  = end[s] - t0 + 1;
        atomicAdd(&bins[t0 * 4 + ((w - 1) >> 3)], 1);
    }
    __syncthreads();

    // exclusive scan over 2048 bins (2 per thread + block scan)
    const int v0 = bins[2 * tid], v1 = bins[2 * tid + 1];
    const int run = v0 + v1;
    int inc = run;
#pragma unroll
    for (int off = 1; off < 32; off <<= 1) {
        const int t = __shfl_up_sync(0xffffffffu, inc, off);
        if (lane >= off) inc += t;
    }
    if (lane == 31) aux[wrp] = inc;
    __syncthreads();
    if (wrp == 0) {
        int a = aux[lane];
#pragma unroll
        for (int off = 1; off < 32; off <<= 1) {
            const int t = __shfl_up_sync(0xffffffffu, a, off);
            if (lane >= off) a += t;
        }
        aux[lane] = a;
    }
    __syncthreads();
    const int ex = inc - run + (wrp ? aux[wrp - 1] : 0);
    bins[2 * tid]     = ex;
    bins[2 * tid + 1] = ex + v0;
    __syncthreads();

    // snapshot per-t0 span offsets before scatter mutates bins
    if (tid < TT) t0_off[tid] = bins[tid * 4];
    if (tid == 0) t0_off[TT] = SS;
    __syncthreads();

    // scatter -> g_sorted (sorted by t0, then w-tier)
    for (int s = tid; s < SS; s += 1024) {
        const int t0 = start[s];
        const int w  = end[s] - t0 + 1;
        const int pos = atomicAdd(&bins[t0 * 4 + ((w - 1) >> 3)], 1);
        g_sorted[pos] = s;
    }
    __syncthreads();

    // scan per-t0 group counts with ALL 1024 threads (0 past TT; no divergence)
    int gc = 0;
    if (tid < TT) gc = (t0_off[tid + 1] - t0_off[tid] + GSZ - 1) >> 2;
    int gi = gc;
#pragma unroll
    for (int off = 1; off < 32; off <<= 1) {
        const int t = __shfl_up_sync(0xffffffffu, gi, off);
        if (lane >= off) gi += t;
    }
    if (lane == 31) aux2[wrp] = gi;
    __syncthreads();
    if (wrp == 0) {
        int a = aux2[lane];
#pragma unroll
        for (int off = 1; off < 32; off <<= 1) {
            const int t = __shfl_up_sync(0xffffffffu, a, off);
            if (lane >= off) a += t;
        }
        aux2[lane] = a;
    }
    __syncthreads();
    const int incl = gi + (wrp ? aux2[wrp - 1] : 0);
    const int g0   = incl - gc;

    if (tid < TT) {
        const int b0 = t0_off[tid];
        const int n  = t0_off[tid + 1] - b0;
        for (int k = 0, q = 0; k < n; k += GSZ, ++q)
            g_groups[g0 + q] = make_int4(b0 + k, min(GSZ, n - k), tid, 0);
    }
    if (tid == 1023) g_ngroups = incl;
}

// ---------------------------------------------------------------------------
// Kernel 4: block per (group, batch). 256 threads cover E = 1024 floats.
// Prologue: pack the 4 members' probs into smem float4 p4[32].
// Hot loop per j: 1 LDG.128 (row) + 1 LDS.128 broadcast (p4[j]) + 16 FFMA.
// Padding is exact: duplicated members aren't stored; zero probs past each
// member's width make extra rows contribute 0.0 exactly.
// ---------------------------------------------------------------------------
__global__ __launch_bounds__(256)
void main_kernel(const float* __restrict__ x,
                 const int* __restrict__ end,
                 float* __restrict__ out) {
    const int gidx = blockIdx.x;
    if (gidx >= g_ngroups) return;
    const int b = blockIdx.y;

    __shared__ float4 p4[32];
    __shared__ int sh_s[GSZ];
    __shared__ int sh_info[3];           // t0, wmax, cnt

    const int tid = threadIdx.x;

    if (tid < 32) {
        const int4 gd = g_groups[gidx];
        const int sb = gd.x, cnt = gd.y, t0 = gd.z;
        const int s0 = g_sorted[sb];
        const int s1 = g_sorted[sb + min(1, cnt - 1)];
        const int s2 = g_sorted[sb + min(2, cnt - 1)];
        const int s3 = g_sorted[sb + min(3, cnt - 1)];
        if (tid == 0) {
            sh_s[0] = s0; sh_s[1] = s1; sh_s[2] = s2; sh_s[3] = s3;
            const int w0 = end[s0], w1 = end[s1], w2 = end[s2], w3 = end[s3];
            sh_info[0] = t0;
            sh_info[1] = max(max(w0, w1), max(w2, w3)) - t0 + 1;   // wmax
            sh_info[2] = cnt;
        }
        const float* __restrict__ pb = g_probs + (size_t)b * SS * 32;
        float4 q;
        q.x = pb[(size_t)s0 * 32 + tid];
        q.y = pb[(size_t)s1 * 32 + tid];
        q.z = pb[(size_t)s2 * 32 + tid];
        q.w = pb[(size_t)s3 * 32 + tid];
        p4[tid] = q;
    }
    __syncthreads();

    const int t0   = sh_info[0];
    const int wmax = sh_info[1];
    const int cnt  = sh_info[2];

    const float4* __restrict__ xb =
        reinterpret_cast<const float4*>(x) + ((size_t)b * TT + t0) * 256 + tid;

    float4 a0 = make_float4(0.f,0.f,0.f,0.f);
    float4 a1 = make_float4(0.f,0.f,0.f,0.f);
    float4 a2 = make_float4(0.f,0.f,0.f,0.f);
    float4 a3 = make_float4(0.f,0.f,0.f,0.f);

#pragma unroll 2
    for (int j = 0; j < wmax; ++j) {
        const float4 v = xb[(size_t)j * 256];
        const float4 q = p4[j];
        a0.x += q.x * v.x; a0.y += q.x * v.y; a0.z += q.x * v.z; a0.w += q.x * v.w;
        a1.x += q.y * v.x; a1.y += q.y * v.y; a1.z += q.y * v.z; a1.w += q.y * v.w;
        a2.x += q.z * v.x; a2.y += q.z * v.y; a2.z += q.z * v.z; a2.w += q.z * v.w;
        a3.x += q.w * v.x; a3.y += q.w * v.y; a3.z += q.w * v.z; a3.w += q.w * v.w;
    }

    float4* __restrict__ o4 =
        reinterpret_cast<float4*>(out) + (size_t)b * SS * 256 + tid;
    o4[(size_t)sh_s[0] * 256] = a0;
    if (cnt > 1) o4[(size_t)sh_s[1] * 256] = a1;
    if (cnt > 2) o4[(size_t)sh_s[2] * 256] = a2;
    if (cnt > 3) o4[(size_t)sh_s[3] * 256] = a3;
}

// ---------------------------------------------------------------------------
// Launch
// Inputs (metadata order): x (B,T,E) f32, W (E,1) f32, b (1,) f32,
//                          start (S,) i32, end (S,) i32
// Output: (B, S, E) f32
// ---------------------------------------------------------------------------
extern "C" void kernel_launch(void* const* d_in, const int* in_sizes, int n_in,
                              void* d_out, int out_size) {
    const float* x     = (const float*)d_in[0];
    const float* W     = (const float*)d_in[1];
    const float* bias  = (const float*)d_in[2];
    const int*   start = (const int*)d_in[3];
    const int*   end   = (const int*)d_in[4];
    float*       out   = (float*)d_out;

    score_kernel<<<(BB * TT) / 8, 256>>>(x, W, bias);
    prob_kernel<<<(BB * SS) / 8, 256>>>(start, end);
    sort_kernel<<<1, 1024>>>(start, end);

    dim3 grid(NGROUPS_MAX, BB);
    main_kernel<<<grid, 256>>>(x, end, out);
}